// round 2
// baseline (speedup 1.0000x reference)
#include <cuda_runtime.h>
#include <math.h>

#define BB 64
#define NN 16800
#define CC 21
#define CHUNK 512
#define SS 33          // ceil(16800/512)
#define FP32_EPS 1.1920928955078125e-07f

// scratch (no cudaMalloc allowed)
__device__ unsigned int g_bits[BB * NN];      // labels_neg as fp32 bits (all >= +0)
__device__ float g_part_lb[BB * SS];          // partial sum pos*smoothl1
__device__ float g_part_cp[BB * SS];          // partial sum pos*ce
__device__ int   g_part_pn[BB * SS];          // partial pos count
__device__ float g_batch[BB * 3];             // per-batch (total, bbox, label)

__device__ __forceinline__ float sl1f(float d) {
    float a = fabsf(d);
    return a < 1.0f ? 0.5f * d * d : a - 0.5f;
}

// ---------------------------------------------------------------------------
// K1: stream everything once. One block = one 512-anchor chunk of one batch.
// float4 warp-cooperative staging of 21-float label rows: 168 float4 per
// 32-anchor tile (16B-aligned since 32*21*4 % 16 == 0, NN % 32 == 0 so every
// active tile is full). Shared reads at stride 21 are conflict-free
// (gcd(21,32)=1).
// ---------------------------------------------------------------------------
__global__ __launch_bounds__(256) void k1_main(
    const float* __restrict__ p_bboxs,
    const float* __restrict__ g_bboxs,
    const float* __restrict__ p_labels,
    const int*   __restrict__ g_labels,
    const float* __restrict__ ancs)
{
    __shared__ float sh[8][672];          // 8 warps x 32 anchors x 21 floats
    __shared__ float red_f[256];
    __shared__ float red_f2[256];
    __shared__ int   red_i[256];

    const int b     = blockIdx.y;
    const int start = blockIdx.x * CHUNK;
    const int end   = min(start + CHUNK, NN);
    const int tid   = threadIdx.x;
    const int w     = tid >> 5;
    const int l     = tid & 31;

    float lb = 0.0f, cp = 0.0f;
    int   pn = 0;

    const float* plab_b = p_labels + (size_t)b * NN * CC;

    for (int cs = start; cs < end; cs += 256) {
        const int ag = cs + w * 32;                 // this warp's anchor tile
        const bool active = (ag < end);             // full 32-anchor tile or none

        if (active) {
            // vectorized stage: 168 float4 = 672 floats
            const float4* src4 = (const float4*)(plab_b + (size_t)ag * CC);
            float4* dst4 = (float4*)&sh[w][0];
            #pragma unroll
            for (int j = 0; j < 5; j++)
                dst4[l + 32 * j] = src4[l + 32 * j];
            if (l < 8)
                dst4[160 + l] = src4[160 + l];
        }
        __syncwarp();

        if (active) {
            const int n = ag + l;
            // regression targets + SmoothL1
            float4 a4 = ((const float4*)ancs)[n];
            float4 g4 = ((const float4*)g_bboxs)[(size_t)b * NN + n];
            float4 p4 = ((const float4*)p_bboxs)[(size_t)b * NN + n];
            float tx = 10.0f * (g4.x - a4.x) / a4.z;
            float ty = 10.0f * (g4.y - a4.y) / a4.w;
            float tw = 5.0f * logf(g4.z / a4.z);
            float th = 5.0f * logf(g4.w / a4.w);
            float sl1 = sl1f(p4.x - tx) + sl1f(p4.y - ty) +
                        sl1f(p4.z - tw) + sl1f(p4.w - th);

            const int lab = g_labels[(size_t)b * NN + n];

            // cross entropy = logsumexp - x[lab]
            const float* xr = &sh[w][l * CC];
            float m = xr[0];
            #pragma unroll
            for (int c = 1; c < CC; c++) m = fmaxf(m, xr[c]);
            float s = 0.0f;
            #pragma unroll
            for (int c = 0; c < CC; c++) s += expf(xr[c] - m);
            float ce = m + logf(s) - xr[lab];

            const bool pos = lab > 0;
            float neg = pos ? 0.0f : ce;            // ce >= 0 -> bit order = value order
            g_bits[(size_t)b * NN + n] = __float_as_uint(neg);
            if (pos) { pn++; lb += sl1; cp += ce; }
        }
        __syncwarp();   // protect sh before next stage iteration
    }

    // deterministic block reduction
    red_f[tid] = lb; red_f2[tid] = cp; red_i[tid] = pn;
    __syncthreads();
    for (int o = 128; o > 0; o >>= 1) {
        if (tid < o) {
            red_f[tid]  += red_f[tid + o];
            red_f2[tid] += red_f2[tid + o];
            red_i[tid]  += red_i[tid + o];
        }
        __syncthreads();
    }
    if (tid == 0) {
        int idx = b * SS + blockIdx.x;
        g_part_lb[idx] = red_f[0];
        g_part_cp[idx] = red_f2[0];
        g_part_pn[idx] = red_i[0];
    }
}

// ---------------------------------------------------------------------------
// K2: one block per batch (1024 threads). Reduce partials, radix-select the
// k-th largest of labels_neg, sum top-k, emit per-batch scaled losses.
// Sum of top-k values is tie-break invariant -> equals the reference's
// double-argsort hard-negative mining contribution.
// ---------------------------------------------------------------------------
__global__ __launch_bounds__(1024) void k2_select()
{
    const int b   = blockIdx.x;
    const int tid = threadIdx.x;

    __shared__ float rf[1024];
    __shared__ float rf2[1024];
    __shared__ int   ri[1024];
    __shared__ unsigned int hist[256];
    __shared__ unsigned int s_prefix;
    __shared__ int s_kr;

    // reduce the 33 partials
    float lb = 0.0f, cp = 0.0f; int pn = 0;
    if (tid < SS) {
        lb = g_part_lb[b * SS + tid];
        cp = g_part_cp[b * SS + tid];
        pn = g_part_pn[b * SS + tid];
    }
    rf[tid] = lb; rf2[tid] = cp; ri[tid] = pn;
    __syncthreads();
    for (int o = 512; o > 0; o >>= 1) {
        if (tid < o) { rf[tid] += rf[tid + o]; rf2[tid] += rf2[tid + o]; ri[tid] += ri[tid + o]; }
        __syncthreads();
    }
    const int   pn_t = ri[0];
    const float lb_t = rf[0];
    const float cp_t = rf2[0];
    __syncthreads();

    if (pn_t == 0) {
        if (tid == 0) {
            g_batch[b * 3 + 0] = 0.0f;
            g_batch[b * 3 + 1] = 0.0f;
            g_batch[b * 3 + 2] = 0.0f;
        }
        return;
    }

    const int k = min(3 * pn_t, NN);
    const unsigned int* vals = g_bits + (size_t)b * NN;

    // 4-pass MSB radix select for k-th largest (values are nonneg fp32 bits)
    unsigned int prefix = 0;
    int kr = k;
    for (int pass = 0; pass < 4; pass++) {
        const int shift = 24 - 8 * pass;
        if (tid < 256) hist[tid] = 0;
        __syncthreads();
        const unsigned int pmask = (pass == 0) ? 0u : (0xFFFFFFFFu << (shift + 8));
        for (int i = tid; i < NN; i += 1024) {
            unsigned int v = vals[i];
            if ((v & pmask) == prefix) atomicAdd(&hist[(v >> shift) & 255u], 1u);
        }
        __syncthreads();
        if (tid == 0) {
            int rem = kr;
            int d = 255;
            for (; d > 0; d--) {
                int c = (int)hist[d];
                if (rem <= c) break;
                rem -= c;
            }
            s_prefix = prefix | ((unsigned int)d << shift);
            s_kr = rem;
        }
        __syncthreads();
        prefix = s_prefix;
        kr = s_kr;
        __syncthreads();
    }
    const unsigned int T = prefix;

    // sum of values strictly greater than T (deterministic reduction)
    float sgt = 0.0f;
    for (int i = tid; i < NN; i += 1024) {
        unsigned int v = vals[i];
        if (v > T) sgt += __uint_as_float(v);
    }
    rf[tid] = sgt;
    __syncthreads();
    for (int o = 512; o > 0; o >>= 1) {
        if (tid < o) rf[tid] += rf[tid + o];
        __syncthreads();
    }

    if (tid == 0) {
        float topk = rf[0] + (float)kr * __uint_as_float(T);
        float loss_labels = cp_t + topk;            // positives CE + mined negatives CE
        float posf = fmaxf((float)pn_t, FP32_EPS);
        float inv = 1.0f / posf;                    // num_mask = 1 here
        g_batch[b * 3 + 0] = (lb_t + loss_labels) * inv;
        g_batch[b * 3 + 1] = lb_t * inv;
        g_batch[b * 3 + 2] = loss_labels * inv;
    }
}

// ---------------------------------------------------------------------------
// K3: mean over batches -> 3 scalars
// ---------------------------------------------------------------------------
__global__ void k3_final(float* __restrict__ out)
{
    __shared__ float r0[64], r1[64], r2[64];
    const int t = threadIdx.x;
    r0[t] = g_batch[t * 3 + 0];
    r1[t] = g_batch[t * 3 + 1];
    r2[t] = g_batch[t * 3 + 2];
    __syncthreads();
    for (int o = 32; o > 0; o >>= 1) {
        if (t < o) { r0[t] += r0[t + o]; r1[t] += r1[t + o]; r2[t] += r2[t + o]; }
        __syncthreads();
    }
    if (t == 0) {
        const float inv = 1.0f / (float)BB;
        out[0] = r0[0] * inv;
        out[1] = r1[0] * inv;
        out[2] = r2[0] * inv;
    }
}

extern "C" void kernel_launch(void* const* d_in, const int* in_sizes, int n_in,
                              void* d_out, int out_size)
{
    const float* p_bboxs  = (const float*)d_in[0];
    const float* g_bboxs  = (const float*)d_in[1];
    const float* p_labels = (const float*)d_in[2];
    const int*   g_labels = (const int*)d_in[3];
    const float* ancs     = (const float*)d_in[4];
    float* out = (float*)d_out;

    dim3 g1(SS, BB);
    k1_main<<<g1, 256>>>(p_bboxs, g_bboxs, p_labels, g_labels, ancs);
    k2_select<<<BB, 1024>>>();
    k3_final<<<1, 64>>>(out);
}